// round 12
// baseline (speedup 1.0000x reference)
#include <cuda_runtime.h>
#include <cuda_bf16.h>
#include <math.h>
#include <stdint.h>

#define NLAYERS 4
#define DMODEL  256
#define DINNER  512
#define DSTATE  16
#define DCONV   4
#define BATCH   64
#define SEQ     900
#define TOKENS  (BATCH * SEQ)   // 57600
#define GB      2               // batch groups (streams)
#define GBATCH  (BATCH / GB)    // 32
#define GTOK    (GBATCH * SEQ)  // 28800
#define LN_EPS  1e-5f
#define LOG2E   1.4426950408889634f

// ---------------- device scratch ----------------
__device__ float g_x  [TOKENS * DMODEL];
__device__ __nv_bfloat16 g_xb[TOKENS * DMODEL];
__device__ __nv_bfloat16 g_xz[TOKENS * 2 * DINNER];
__device__ __nv_bfloat16 g_xs[TOKENS * DINNER];
__device__ float g_ssm[TOKENS * 2 * DSTATE];
__device__ __nv_bfloat16 g_yb[TOKENS * DINNER];
// K-major bf16 weights (bf16x2-packed u32)
__device__ uint32_t g_wbi[NLAYERS * 2 * DINNER * (DMODEL / 2)];
__device__ uint32_t g_wbo[NLAYERS * DMODEL * (DINNER / 2)];
__device__ uint32_t g_wbx[NLAYERS * 2 * DSTATE * (DINNER / 2)];

__device__ __forceinline__ uint32_t packbf(float lo, float hi) {
    uint32_t r;
    asm("cvt.rn.bf16x2.f32 %0, %1, %2;" : "=r"(r) : "f"(hi), "f"(lo));
    return r;
}
__device__ __forceinline__ uint32_t smem_u32(const void* p) {
    uint32_t a;
    asm("{ .reg .u64 t; cvta.to.shared.u64 t, %1; cvt.u32.u64 %0, t; }" : "=r"(a) : "l"(p));
    return a;
}
#define CP_ASYNC16(dst, src) \
    asm volatile("cp.async.cg.shared.global [%0], [%1], 16;" :: "r"(dst), "l"(src))
#define CP_COMMIT() asm volatile("cp.async.commit_group;" ::: "memory")
#define CP_WAIT1()  asm volatile("cp.async.wait_group 1;" ::: "memory")

// ---------------- weight converts ----------------
__global__ void convert_in_w_kernel(const float* __restrict__ w, uint32_t* __restrict__ wt)
{
    const int PER = 2 * DINNER * (DMODEL / 2);
    int idx = blockIdx.x * blockDim.x + threadIdx.x;
    if (idx >= NLAYERS * PER) return;
    int l  = idx / PER;
    int r  = idx % PER;
    int n  = r % (2 * DINNER);
    int k2 = r / (2 * DINNER);
    const float* wl = w + (size_t)l * DMODEL * 2 * DINNER;
    wt[(size_t)l * PER + (size_t)n * (DMODEL / 2) + k2] =
        packbf(wl[(size_t)(2 * k2) * 2 * DINNER + n], wl[(size_t)(2 * k2 + 1) * 2 * DINNER + n]);
}
__global__ void convert_out_w_kernel(const float* __restrict__ w, uint32_t* __restrict__ wt)
{
    const int PER = DMODEL * (DINNER / 2);
    int idx = blockIdx.x * blockDim.x + threadIdx.x;
    if (idx >= NLAYERS * PER) return;
    int l  = idx / PER;
    int r  = idx % PER;
    int n  = r % DMODEL;
    int k2 = r / DMODEL;
    const float* wl = w + (size_t)l * DINNER * DMODEL;
    wt[(size_t)l * PER + (size_t)n * (DINNER / 2) + k2] =
        packbf(wl[(size_t)(2 * k2) * DMODEL + n], wl[(size_t)(2 * k2 + 1) * DMODEL + n]);
}
__global__ void convert_xp_w_kernel(const float* __restrict__ w, uint32_t* __restrict__ wt)
{
    const int PER = 32 * (DINNER / 2);
    int idx = blockIdx.x * blockDim.x + threadIdx.x;
    if (idx >= NLAYERS * PER) return;
    int l  = idx / PER;
    int r  = idx % PER;
    int n  = r % 32;
    int k2 = r / 32;
    const float* wl = w + (size_t)l * DINNER * 32;
    wt[(size_t)l * PER + (size_t)n * (DINNER / 2) + k2] =
        packbf(wl[(size_t)(2 * k2) * 32 + n], wl[(size_t)(2 * k2 + 1) * 32 + n]);
}

// ---------------- embed ----------------
__global__ void embed_kernel(const int* __restrict__ grid,
                             const float* __restrict__ ce,
                             const float* __restrict__ pe)
{
    int idx = blockIdx.x * blockDim.x + threadIdx.x;
    if (idx >= TOKENS * (DMODEL / 4)) return;
    int tok = idx >> 6;
    int c4  = (idx & 63) * 4;
    int s   = tok % SEQ;
    int g   = grid[tok];
    float4 a = *(const float4*)&ce[g * DMODEL + c4];
    float4 p = *(const float4*)&pe[s * DMODEL + c4];
    float4 r; r.x = a.x + p.x; r.y = a.y + p.y; r.z = a.z + p.z; r.w = a.w + p.w;
    *(float4*)&g_x[tok * DMODEL + c4] = r;
    *(uint2*)&g_xb[tok * DMODEL + c4] = make_uint2(packbf(r.x, r.y), packbf(r.z, r.w));
}

// ---------------- bf16 GEMM: 128xNT tile, GBK=64, 3-stage cp.async + ldmatrix ----------------
// MODE 1: bf16 out. MODE 2: fp32 + softplus cols<16. MODE 3: fused out_proj+residual+LN.
#define ABYTES 18432            // 128 rows * 144B

template<int NT>
__device__ __forceinline__ void gemm_stage64(uint32_t st,
                                             const __nv_bfloat16* __restrict__ A,
                                             const __nv_bfloat16* __restrict__ Bw,
                                             int row0, int col0, int K, int k0, int tid)
{
#pragma unroll
    for (int p = 0; p < 4; p++) {
        int i = tid + p * 256;
        int r = i >> 3, cc = (i & 7) << 4;
        CP_ASYNC16(st + r * 144 + cc, (const char*)(A + (size_t)(row0 + r) * K + k0) + cc);
    }
#pragma unroll
    for (int p = 0; p < NT / 32; p++) {
        int i = tid + p * 256;
        int r = i >> 3, cc = (i & 7) << 4;
        CP_ASYNC16(st + ABYTES + r * 144 + cc, (const char*)(Bw + (size_t)(col0 + r) * K + k0) + cc);
    }
}

template<int NT, int MODE>
__global__ __launch_bounds__(256, (NT == 256) ? 1 : 2) void gemm_bf16_kernel(
    const __nv_bfloat16* __restrict__ A, const __nv_bfloat16* __restrict__ Bw,
    const float* __restrict__ bias, void* __restrict__ Cv,
    int N, int K, int row_base,
    const float* __restrict__ gam, const float* __restrict__ bet,
    __nv_bfloat16* __restrict__ mirror)
{
    constexpr int WMI    = 4;
    constexpr int WNJ    = (NT == 256) ? 8 : ((NT == 128) ? 4 : 4);
    constexpr int WNSPAN = (NT == 256) ? 64 : 32;
    constexpr int NBJJ   = WNSPAN / 16;
    constexpr int SSTAGE = (128 + NT) * 144;
    constexpr int WMI_E  = (NT == 32) ? 1 : WMI;   // xproj uses 8 warps over m (warp=wm)

    extern __shared__ char smem[];
    uint32_t sb = smem_u32(smem);

    int tid  = threadIdx.x;
    int lane = tid & 31;
    int warp = tid >> 5;
    int wm   = (NT >= 128) ? (warp >> 2) : warp;
    int wn   = (NT >= 128) ? (warp & 3) : 0;
    int row0 = row_base + blockIdx.y * 128;
    int col0 = blockIdx.x * NT;
    int grp  = lane >> 2;
    int qid  = lane & 3;

    float acc[WMI_E][WNJ][4];
#pragma unroll
    for (int i = 0; i < WMI_E; i++)
#pragma unroll
        for (int j = 0; j < WNJ; j++)
#pragma unroll
            for (int r = 0; r < 4; r++) acc[i][j][r] = 0.f;

    int NC = K / 64;
    gemm_stage64<NT>(sb, A, Bw, row0, col0, K, 0, tid);            CP_COMMIT();
    gemm_stage64<NT>(sb + SSTAGE, A, Bw, row0, col0, K, 64, tid);  CP_COMMIT();

    int a_row  = wm * (WMI_E * 16) + (lane & 15);
    int a_koff = (lane >> 4) << 4;
    int b_row0 = wn * WNSPAN + ((lane >> 4) << 3) + (lane & 7);
    int b_koff = ((lane >> 3) & 1) << 4;

    for (int c = 0; c < NC; c++) {
        CP_WAIT1();
        __syncthreads();
        if (c + 2 < NC)
            gemm_stage64<NT>(sb + ((c + 2) % 3) * SSTAGE, A, Bw, row0, col0, K, (c + 2) * 64, tid);
        CP_COMMIT();
        uint32_t stA = sb + (c % 3) * SSTAGE;
        uint32_t stB = stA + ABYTES;
#pragma unroll
        for (int ks = 0; ks < 4; ks++) {
            uint32_t af[WMI_E][4];
#pragma unroll
            for (int i = 0; i < WMI_E; i++) {
                uint32_t addr = stA + (a_row + i * 16) * 144 + ks * 32 + a_koff;
                asm volatile("ldmatrix.sync.aligned.m8n8.x4.shared.b16 {%0,%1,%2,%3}, [%4];"
                             : "=r"(af[i][0]), "=r"(af[i][1]), "=r"(af[i][2]), "=r"(af[i][3])
                             : "r"(addr));
            }
            uint32_t bf_[NBJJ][4];
#pragma unroll
            for (int jj = 0; jj < NBJJ; jj++) {
                uint32_t addr = stB + (b_row0 + jj * 16) * 144 + ks * 32 + b_koff;
                asm volatile("ldmatrix.sync.aligned.m8n8.x4.shared.b16 {%0,%1,%2,%3}, [%4];"
                             : "=r"(bf_[jj][0]), "=r"(bf_[jj][1]), "=r"(bf_[jj][2]), "=r"(bf_[jj][3])
                             : "r"(addr));
            }
#pragma unroll
            for (int i = 0; i < WMI_E; i++)
#pragma unroll
                for (int j = 0; j < WNJ; j++) {
                    asm volatile(
                        "mma.sync.aligned.m16n8k16.row.col.f32.bf16.bf16.f32 "
                        "{%0,%1,%2,%3}, {%4,%5,%6,%7}, {%8,%9}, {%0,%1,%2,%3};"
                        : "+f"(acc[i][j][0]), "+f"(acc[i][j][1]),
                          "+f"(acc[i][j][2]), "+f"(acc[i][j][3])
                        : "r"(af[i][0]), "r"(af[i][1]), "r"(af[i][2]), "r"(af[i][3]),
                          "r"(bf_[j >> 1][(j & 1) * 2]), "r"(bf_[j >> 1][(j & 1) * 2 + 1]));
                }
        }
        __syncthreads();
    }

    if (MODE == 3) {
        float* Xr = (float*)Cv;   // g_x
#pragma unroll
        for (int i = 0; i < WMI_E; i++) {
            int r0 = row0 + wm * 64 + i * 16 + grp;
#pragma unroll
            for (int j = 0; j < WNJ; j++) {
                int cg = col0 + wn * WNSPAN + j * 8 + qid * 2;
                float b0 = bias[cg], b1 = bias[cg + 1];
                float2 x0 = *(const float2*)&Xr[(size_t)r0 * DMODEL + cg];
                float2 x1 = *(const float2*)&Xr[(size_t)(r0 + 8) * DMODEL + cg];
                acc[i][j][0] += b0 + x0.x;
                acc[i][j][1] += b1 + x0.y;
                acc[i][j][2] += b0 + x1.x;
                acc[i][j][3] += b1 + x1.y;
            }
        }
        float2* sred = (float2*)smem;
#pragma unroll
        for (int i = 0; i < WMI_E; i++) {
            float s0 = 0.f, q0 = 0.f, s1 = 0.f, q1 = 0.f;
#pragma unroll
            for (int j = 0; j < WNJ; j++) {
                s0 += acc[i][j][0] + acc[i][j][1];
                q0 += acc[i][j][0] * acc[i][j][0] + acc[i][j][1] * acc[i][j][1];
                s1 += acc[i][j][2] + acc[i][j][3];
                q1 += acc[i][j][2] * acc[i][j][2] + acc[i][j][3] * acc[i][j][3];
            }
            s0 += __shfl_xor_sync(0xFFFFFFFF, s0, 1); s0 += __shfl_xor_sync(0xFFFFFFFF, s0, 2);
            q0 += __shfl_xor_sync(0xFFFFFFFF, q0, 1); q0 += __shfl_xor_sync(0xFFFFFFFF, q0, 2);
            s1 += __shfl_xor_sync(0xFFFFFFFF, s1, 1); s1 += __shfl_xor_sync(0xFFFFFFFF, s1, 2);
            q1 += __shfl_xor_sync(0xFFFFFFFF, q1, 1); q1 += __shfl_xor_sync(0xFFFFFFFF, q1, 2);
            if (qid == 0) {
                int lr = wm * 64 + i * 16 + grp;
                sred[lr * 4 + wn]       = make_float2(s0, q0);
                sred[(lr + 8) * 4 + wn] = make_float2(s1, q1);
            }
        }
        __syncthreads();
#pragma unroll
        for (int i = 0; i < WMI_E; i++) {
            int lr0 = wm * 64 + i * 16 + grp;
            float mu[2], rs[2];
#pragma unroll
            for (int rr = 0; rr < 2; rr++) {
                int lr = lr0 + rr * 8;
                float2 p0 = sred[lr * 4 + 0], p1 = sred[lr * 4 + 1];
                float2 p2 = sred[lr * 4 + 2], p3 = sred[lr * 4 + 3];
                float S  = p0.x + p1.x + p2.x + p3.x;
                float SS = p0.y + p1.y + p2.y + p3.y;
                float m  = S * (1.f / DMODEL);
                float v  = SS * (1.f / DMODEL) - m * m;
                mu[rr] = m;
                rs[rr] = rsqrtf(v + LN_EPS);
            }
            int r0 = row0 + lr0;
#pragma unroll
            for (int j = 0; j < WNJ; j++) {
                int cg = col0 + wn * WNSPAN + j * 8 + qid * 2;
                float g0 = gam[cg], g1 = gam[cg + 1];
                float t0 = bet[cg], t1 = bet[cg + 1];
                float o00 = (acc[i][j][0] - mu[0]) * rs[0] * g0 + t0;
                float o01 = (acc[i][j][1] - mu[0]) * rs[0] * g1 + t1;
                float o10 = (acc[i][j][2] - mu[1]) * rs[1] * g0 + t0;
                float o11 = (acc[i][j][3] - mu[1]) * rs[1] * g1 + t1;
                *(float2*)&Xr[(size_t)r0 * DMODEL + cg]       = make_float2(o00, o01);
                *(float2*)&Xr[(size_t)(r0 + 8) * DMODEL + cg] = make_float2(o10, o11);
                *(uint32_t*)&mirror[(size_t)r0 * DMODEL + cg]       = packbf(o00, o01);
                *(uint32_t*)&mirror[(size_t)(r0 + 8) * DMODEL + cg] = packbf(o10, o11);
            }
        }
        return;
    }

#pragma unroll
    for (int i = 0; i < WMI_E; i++) {
        int rg0 = row0 + wm * (WMI_E * 16) + i * 16 + grp;
#pragma unroll
        for (int j = 0; j < WNJ; j++) {
            int cg = col0 + wn * WNSPAN + j * 8 + qid * 2;
            float b0 = bias[cg], b1 = bias[cg + 1];
            float v00 = acc[i][j][0] + b0, v01 = acc[i][j][1] + b1;
            float v10 = acc[i][j][2] + b0, v11 = acc[i][j][3] + b1;
            if (MODE == 2 && j < 2) {
                v00 = (v00 > 20.f) ? v00 : log1pf(__expf(v00));
                v01 = (v01 > 20.f) ? v01 : log1pf(__expf(v01));
                v10 = (v10 > 20.f) ? v10 : log1pf(__expf(v10));
                v11 = (v11 > 20.f) ? v11 : log1pf(__expf(v11));
            }
            if (MODE == 1) {
                __nv_bfloat16* Cb = (__nv_bfloat16*)Cv;
                *(uint32_t*)&Cb[(size_t)rg0 * N + cg]       = packbf(v00, v01);
                *(uint32_t*)&Cb[(size_t)(rg0 + 8) * N + cg] = packbf(v10, v11);
            } else {
                float* C = (float*)Cv;
                *(float2*)&C[(size_t)rg0 * N + cg]       = make_float2(v00, v01);
                *(float2*)&C[(size_t)(rg0 + 8) * N + cg] = make_float2(v10, v11);
            }
        }
    }
}

// ---------------- depthwise causal conv(4) + silu ----------------
__global__ void conv_silu_kernel(const float* __restrict__ cw,
                                 const float* __restrict__ cb, int l, int tokOff)
{
    int idx = blockIdx.x * blockDim.x + threadIdx.x;
    if (idx >= (GTOK / 4) * 128) return;
    int g128 = idx & 127;
    int q    = idx >> 7;
    int t0   = tokOff + q * 4;
    int b    = t0 / SEQ;
    int s0   = t0 % SEQ;
    int c    = g128 * 4;

    float4 w0 = *(const float4*)&cw[(l * DINNER + c + 0) * DCONV];
    float4 w1 = *(const float4*)&cw[(l * DINNER + c + 1) * DCONV];
    float4 w2 = *(const float4*)&cw[(l * DINNER + c + 2) * DCONV];
    float4 w3 = *(const float4*)&cw[(l * DINNER + c + 3) * DCONV];
    float wa[4][4] = {{w0.x,w0.y,w0.z,w0.w},{w1.x,w1.y,w1.z,w1.w},
                      {w2.x,w2.y,w2.z,w2.w},{w3.x,w3.y,w3.z,w3.w}};
    float bs0 = cb[l * DINNER + c + 0];
    float bs1 = cb[l * DINNER + c + 1];
    float bs2 = cb[l * DINNER + c + 2];
    float bs3 = cb[l * DINNER + c + 3];

    float rowv[7][4];
#pragma unroll
    for (int k = 0; k < 7; k++) {
        int s = s0 - 3 + k;
        if (s >= 0) {
            uint2 v = *(const uint2*)&g_xz[(size_t)(b * SEQ + s) * 2 * DINNER + c];
            float2 p0 = __bfloat1622float2(*(__nv_bfloat162*)&v.x);
            float2 p1 = __bfloat1622float2(*(__nv_bfloat162*)&v.y);
            rowv[k][0] = p0.x; rowv[k][1] = p0.y; rowv[k][2] = p1.x; rowv[k][3] = p1.y;
        } else {
            rowv[k][0] = rowv[k][1] = rowv[k][2] = rowv[k][3] = 0.f;
        }
    }
#pragma unroll
    for (int t = 0; t < 4; t++) {
        float o0 = bs0, o1 = bs1, o2 = bs2, o3 = bs3;
#pragma unroll
        for (int k = 0; k < DCONV; k++) {
            o0 += rowv[t + k][0] * wa[0][k];
            o1 += rowv[t + k][1] * wa[1][k];
            o2 += rowv[t + k][2] * wa[2][k];
            o3 += rowv[t + k][3] * wa[3][k];
        }
        o0 = o0 * (1.f / (1.f + __expf(-o0)));
        o1 = o1 * (1.f / (1.f + __expf(-o1)));
        o2 = o2 * (1.f / (1.f + __expf(-o2)));
        o3 = o3 * (1.f / (1.f + __expf(-o3)));
        *(uint2*)&g_xs[(size_t)(b * SEQ + s0 + t) * DINNER + c] =
            make_uint2(packbf(o0, o1), packbf(o2, o3));
    }
}

// ---------------- selective scan: cp.async chunked SMEM pipeline ----------------
#define SCH 18
#define SST 11520

__device__ __forceinline__ void scan_stage(uint32_t dst, int b, int d0, int t0, int tid)
{
    const char* ssrc = (const char*)(g_ssm + (size_t)(b * SEQ + t0) * 32);
#pragma unroll 2
    for (int i = tid; i < 144; i += 128)
        CP_ASYNC16(dst + i * 16, ssrc + i * 16);
#pragma unroll 3
    for (int i = tid; i < 288; i += 128) {
        int r = i >> 4, o = (i & 15) << 4;
        CP_ASYNC16(dst + 2304 + r * 256 + o,
                   (const char*)(g_xs + (size_t)(b * SEQ + t0 + r) * DINNER + d0) + o);
    }
#pragma unroll 3
    for (int i = tid; i < 288; i += 128) {
        int r = i >> 4, o = (i & 15) << 4;
        CP_ASYNC16(dst + 6912 + r * 256 + o,
                   (const char*)(g_xz + (size_t)(b * SEQ + t0 + r) * 2 * DINNER + DINNER + d0) + o);
    }
}

__global__ __launch_bounds__(128) void scan_kernel(const float* __restrict__ A_log,
                                                   const float* __restrict__ Dp, int l,
                                                   int batch0)
{
    extern __shared__ char ssm_smem[];
    uint32_t sb = smem_u32(ssm_smem);
    int tid = threadIdx.x;
    int b   = batch0 + blockIdx.x;
    int d0  = blockIdx.y * 128;
    int d   = d0 + tid;

    const float* Al = A_log + (size_t)(l * DINNER + d) * DSTATE;
    float a2[DSTATE];
#pragma unroll
    for (int n = 0; n < DSTATE; n++) a2[n] = -__expf(Al[n]) * LOG2E;
    float Dv = Dp[l * DINNER + d];
    float h[DSTATE];
#pragma unroll
    for (int n = 0; n < DSTATE; n++) h[n] = 0.f;

    scan_stage(sb, b, d0, 0, tid);           CP_COMMIT();
    scan_stage(sb + SST, b, d0, SCH, tid);   CP_COMMIT();

    int tok0 = b * SEQ;
    for (int c = 0; c < 50; c++) {
        CP_WAIT1();
        __syncthreads();
        int st = (c & 1);
        const float* ssp = (const float*)(ssm_smem + st * SST);
        const __nv_bfloat16* xsp = (const __nv_bfloat16*)(ssm_smem + st * SST + 2304);
        const __nv_bfloat16* rsp = (const __nv_bfloat16*)(ssm_smem + st * SST + 6912);
        __nv_bfloat16* yp = g_yb + (size_t)(tok0 + c * SCH) * DINNER + d;

#pragma unroll 2
        for (int t = 0; t < SCH; t++) {
            const float4* sp = (const float4*)(ssp + t * 32);
            float4 d0v = sp[0], d1v = sp[1], d2v = sp[2], d3v = sp[3];
            float4 b0v = sp[4], b1v = sp[5], b2v = sp[6], b3v = sp[7];
            float dl[DSTATE] = {d0v.x,d0v.y,d0v.z,d0v.w, d1v.x,d1v.y,d1v.z,d1v.w,
                                d2v.x,d2v.y,d2v.z,d2v.w, d3v.x,d3v.y,d3v.z,d3v.w};
            float bm[DSTATE] = {b0v.x,b0v.y,b0v.z,b0v.w, b1v.x,b1v.y,b1v.z,b1v.w,
                                b2v.x,b2v.y,b2v.z,b2v.w, b3v.x,b3v.y,b3v.z,b3v.w};
            float xv = __bfloat162float(xsp[t * 128 + tid]);
            float rv = __bfloat162float(rsp[t * 128 + tid]);
            float accv = 0.f;
#pragma unroll
            for (int n = 0; n < DSTATE; n++) {
                float e = exp2f(a2[n] * dl[n]);
                h[n] = h[n] * e + xv * bm[n];
                accv += h[n] * bm[n];
            }
            float sl = rv * (1.f / (1.f + __expf(-rv)));
            yp[(size_t)t * DINNER] = __float2bfloat16((accv + Dv * xv) * sl);
        }
        __syncthreads();
        if (c + 2 < 50)
            scan_stage(sb + st * SST, b, d0, (c + 2) * SCH, tid);
        CP_COMMIT();
    }
}

// ---------------- heads ----------------
__global__ void heads_kernel(const float* __restrict__ c1w, const float* __restrict__ c1b,
                             const float* __restrict__ c2w, const float* __restrict__ c2b,
                             const float* __restrict__ q1w, const float* __restrict__ q1b,
                             const float* __restrict__ q2w, const float* __restrict__ q2b,
                             float* __restrict__ out)
{
    __shared__ float fin[DMODEL];
    __shared__ float hc[128], hq[128];
    int b = blockIdx.x, t = threadIdx.x;
    const float* f = g_x + (size_t)(b * SEQ + SEQ - 1) * DMODEL;
    fin[t] = f[t];
    fin[t + 128] = f[t + 128];
    __syncthreads();
    float a1 = c1b[t], a2 = q1b[t];
#pragma unroll 4
    for (int k = 0; k < DMODEL; k++) {
        float fv = fin[k];
        a1 += fv * c1w[k * 128 + t];
        a2 += fv * q1w[k * 128 + t];
    }
    hc[t] = fmaxf(a1, 0.f);
    hq[t] = fmaxf(a2, 0.f);
    __syncthreads();
    if (t == 0) {
        float s = c2b[0];
        for (int k = 0; k < 128; k++) s += hc[k] * c2w[k];
        out[b] = fmaxf(s, 0.f);
    }
    if (t < 10) {
        float s = q2b[t];
        for (int k = 0; k < 128; k++) s += hq[k] * q2w[k * 10 + t];
        out[BATCH + b * 10 + t] = fmaxf(s, 0.f);
    }
}

// ---------------- launch ----------------
extern "C" void kernel_launch(void* const* d_in, const int* in_sizes, int n_in,
                              void* d_out, int out_size)
{
    const int*   grid   = (const int*)  d_in[0];
    const float* ce     = (const float*)d_in[1];
    const float* pe     = (const float*)d_in[2];
    const float* in_w   = (const float*)d_in[3];
    const float* in_b   = (const float*)d_in[4];
    const float* conv_w = (const float*)d_in[5];
    const float* conv_b = (const float*)d_in[6];
    const float* xp_w   = (const float*)d_in[7];
    const float* xp_b   = (const float*)d_in[8];
    const float* A_log  = (const float*)d_in[9];
    const float* Dp     = (const float*)d_in[10];
    const float* out_w  = (const float*)d_in[11];
    const float* out_b  = (const float*)d_in[12];
    const float* ln_g   = (const float*)d_in[13];
    const float* ln_b   = (const float*)d_in[14];
    const float* c1w    = (const float*)d_in[15];
    const float* c1b    = (const float*)d_in[16];
    const float* c2w    = (const float*)d_in[17];
    const float* c2b    = (const float*)d_in[18];
    const float* q1w    = (const float*)d_in[19];
    const float* q1b    = (const float*)d_in[20];
    const float* q2w    = (const float*)d_in[21];
    const float* q2b    = (const float*)d_in[22];
    float* out = (float*)d_out;

    __nv_bfloat16 *pxb, *pyb, *pxz, *pxs;
    uint32_t *pwbi, *pwbo, *pwbx;
    float *px, *pssm;
    cudaGetSymbolAddress((void**)&px,   g_x);
    cudaGetSymbolAddress((void**)&pxb,  g_xb);
    cudaGetSymbolAddress((void**)&pyb,  g_yb);
    cudaGetSymbolAddress((void**)&pxz,  g_xz);
    cudaGetSymbolAddress((void**)&pxs,  g_xs);
    cudaGetSymbolAddress((void**)&pssm, g_ssm);
    cudaGetSymbolAddress((void**)&pwbi, g_wbi);
    cudaGetSymbolAddress((void**)&pwbo, g_wbo);
    cudaGetSymbolAddress((void**)&pwbx, g_wbx);

    const int SM128 = 3 * (128 + 128) * 144;   // 110592
    const int SM256 = 3 * (128 + 256) * 144;   // 165888
    const int SM32  = 3 * (128 + 32) * 144;    // 69120
    cudaFuncSetAttribute(gemm_bf16_kernel<128, 1>, cudaFuncAttributeMaxDynamicSharedMemorySize, SM128);
    cudaFuncSetAttribute(gemm_bf16_kernel<256, 3>, cudaFuncAttributeMaxDynamicSharedMemorySize, SM256);
    cudaFuncSetAttribute(gemm_bf16_kernel<32, 2>,  cudaFuncAttributeMaxDynamicSharedMemorySize, SM32);

    // fork/join machinery (host objects; created per call, capture-legal)
    cudaStream_t s1;
    cudaStreamCreateWithFlags(&s1, cudaStreamNonBlocking);
    cudaEvent_t evFork, evJoin;
    cudaEventCreateWithFlags(&evFork, cudaEventDisableTiming);
    cudaEventCreateWithFlags(&evJoin, cudaEventDisableTiming);

    // prologue on default stream
    {
        int nA = NLAYERS * 2 * DINNER * (DMODEL / 2);
        convert_in_w_kernel<<<(nA + 255) / 256, 256>>>(in_w, pwbi);
        int nB = NLAYERS * DMODEL * (DINNER / 2);
        convert_out_w_kernel<<<(nB + 255) / 256, 256>>>(out_w, pwbo);
        int nX = NLAYERS * 32 * (DINNER / 2);
        convert_xp_w_kernel<<<(nX + 255) / 256, 256>>>(xp_w, pwbx);
        int n = TOKENS * (DMODEL / 4);
        embed_kernel<<<(n + 255) / 256, 256>>>(grid, ce, pe);
    }
    cudaEventRecord(evFork, 0);
    cudaStreamWaitEvent(s1, evFork, 0);

    // two batch groups, one per stream, full 4-layer stack each
    for (int g = 0; g < GB; g++) {
        cudaStream_t st = (g == 0) ? (cudaStream_t)0 : s1;
        int rowBase = g * GTOK;
        int batch0  = g * GBATCH;

        for (int l = 0; l < NLAYERS; l++) {
            gemm_bf16_kernel<128, 1><<<dim3(8, GTOK / 128), 256, SM128, st>>>(
                pxb, (const __nv_bfloat16*)(pwbi + (size_t)l * 2 * DINNER * (DMODEL / 2)),
                in_b + l * 2 * DINNER, pxz, 2 * DINNER, DMODEL, rowBase,
                nullptr, nullptr, nullptr);

            {
                int n = (GTOK / 4) * 128;
                conv_silu_kernel<<<(n + 255) / 256, 256, 0, st>>>(conv_w, conv_b, l, rowBase);
            }

            gemm_bf16_kernel<32, 2><<<dim3(1, GTOK / 128), 256, SM32, st>>>(
                pxs, (const __nv_bfloat16*)(pwbx + (size_t)l * 32 * (DINNER / 2)),
                xp_b + l * 32, pssm, 32, DINNER, rowBase,
                nullptr, nullptr, nullptr);

            scan_kernel<<<dim3(GBATCH, DINNER / 128), 128, 2 * SST, st>>>(A_log, Dp, l, batch0);

            gemm_bf16_kernel<256, 3><<<dim3(1, GTOK / 128), 256, SM256, st>>>(
                pyb, (const __nv_bfloat16*)(pwbo + (size_t)l * DMODEL * (DINNER / 2)),
                out_b + l * DMODEL, px, DMODEL, DINNER, rowBase,
                ln_g, ln_b, pxb);
        }
    }

    cudaEventRecord(evJoin, s1);
    cudaStreamWaitEvent(0, evJoin, 0);

    heads_kernel<<<BATCH, 128>>>(c1w, c1b, c2w, c2b, q1w, q1b, q2w, q2b, out);

    cudaEventDestroy(evFork);
    cudaEventDestroy(evJoin);
    cudaStreamDestroy(s1);
}

// round 14
// speedup vs baseline: 1.0249x; 1.0249x over previous
#include <cuda_runtime.h>
#include <cuda_bf16.h>
#include <math.h>
#include <stdint.h>

#define NLAYERS 4
#define DMODEL  256
#define DINNER  512
#define DSTATE  16
#define DCONV   4
#define BATCH   64
#define SEQ     900
#define TOKENS  (BATCH * SEQ)   // 57600
#define LN_EPS  1e-5f
#define LOG2E   1.4426950408889634f

// ---------------- device scratch ----------------
__device__ float g_x  [TOKENS * DMODEL];
__device__ __nv_bfloat16 g_xb[TOKENS * DMODEL];
__device__ __nv_bfloat16 g_xz[TOKENS * 2 * DINNER];
__device__ __nv_bfloat16 g_xs[TOKENS * DINNER];
__device__ float g_ssm[TOKENS * 2 * DSTATE];
__device__ __nv_bfloat16 g_yb[TOKENS * DINNER];
// K-major bf16 weights (bf16x2-packed u32)
__device__ uint32_t g_wbi[NLAYERS * 2 * DINNER * (DMODEL / 2)];
__device__ uint32_t g_wbo[NLAYERS * DMODEL * (DINNER / 2)];
__device__ uint32_t g_wbx[NLAYERS * 2 * DSTATE * (DINNER / 2)];

__device__ __forceinline__ uint32_t packbf(float lo, float hi) {
    uint32_t r;
    asm("cvt.rn.bf16x2.f32 %0, %1, %2;" : "=r"(r) : "f"(hi), "f"(lo));
    return r;
}
__device__ __forceinline__ uint32_t smem_u32(const void* p) {
    uint32_t a;
    asm("{ .reg .u64 t; cvta.to.shared.u64 t, %1; cvt.u32.u64 %0, t; }" : "=r"(a) : "l"(p));
    return a;
}
#define CP_ASYNC16(dst, src) \
    asm volatile("cp.async.cg.shared.global [%0], [%1], 16;" :: "r"(dst), "l"(src))
#define CP_COMMIT() asm volatile("cp.async.commit_group;" ::: "memory")
#define CP_WAIT1()  asm volatile("cp.async.wait_group 1;" ::: "memory")

// ---------------- weight converts (2 launches) ----------------
__global__ void convert_in_w_kernel(const float* __restrict__ w, uint32_t* __restrict__ wt)
{
    const int PER = 2 * DINNER * (DMODEL / 2);
    int idx = blockIdx.x * blockDim.x + threadIdx.x;
    if (idx >= NLAYERS * PER) return;
    int l  = idx / PER;
    int r  = idx % PER;
    int n  = r % (2 * DINNER);
    int k2 = r / (2 * DINNER);
    const float* wl = w + (size_t)l * DMODEL * 2 * DINNER;
    wt[(size_t)l * PER + (size_t)n * (DMODEL / 2) + k2] =
        packbf(wl[(size_t)(2 * k2) * 2 * DINNER + n], wl[(size_t)(2 * k2 + 1) * 2 * DINNER + n]);
}
// combined: out_w transpose + xp_w transpose
__global__ void convert_oxw_kernel(const float* __restrict__ wo, uint32_t* __restrict__ wto,
                                   const float* __restrict__ wx, uint32_t* __restrict__ wtx)
{
    const int PERO = DMODEL * (DINNER / 2);    // 65536
    const int PERX = 32 * (DINNER / 2);        // 8192
    int idx = blockIdx.x * blockDim.x + threadIdx.x;
    int totO = NLAYERS * PERO;
    if (idx < totO) {
        int l  = idx / PERO;
        int r  = idx % PERO;
        int n  = r % DMODEL;
        int k2 = r / DMODEL;
        const float* wl = wo + (size_t)l * DINNER * DMODEL;
        wto[(size_t)l * PERO + (size_t)n * (DINNER / 2) + k2] =
            packbf(wl[(size_t)(2 * k2) * DMODEL + n], wl[(size_t)(2 * k2 + 1) * DMODEL + n]);
    } else if (idx < totO + NLAYERS * PERX) {
        int j  = idx - totO;
        int l  = j / PERX;
        int r  = j % PERX;
        int n  = r % 32;
        int k2 = r / 32;
        const float* wl = wx + (size_t)l * DINNER * 32;
        wtx[(size_t)l * PERX + (size_t)n * (DINNER / 2) + k2] =
            packbf(wl[(size_t)(2 * k2) * 32 + n], wl[(size_t)(2 * k2 + 1) * 32 + n]);
    }
}

// ---------------- embed ----------------
__global__ void embed_kernel(const int* __restrict__ grid,
                             const float* __restrict__ ce,
                             const float* __restrict__ pe)
{
    int idx = blockIdx.x * blockDim.x + threadIdx.x;
    if (idx >= TOKENS * (DMODEL / 4)) return;
    int tok = idx >> 6;
    int c4  = (idx & 63) * 4;
    int s   = tok % SEQ;
    int g   = grid[tok];
    float4 a = *(const float4*)&ce[g * DMODEL + c4];
    float4 p = *(const float4*)&pe[s * DMODEL + c4];
    float4 r; r.x = a.x + p.x; r.y = a.y + p.y; r.z = a.z + p.z; r.w = a.w + p.w;
    *(float4*)&g_x[tok * DMODEL + c4] = r;
    *(uint2*)&g_xb[tok * DMODEL + c4] = make_uint2(packbf(r.x, r.y), packbf(r.z, r.w));
}

// ---------------- bf16 GEMM (in_proj / xproj): 128xNT tile, GBK=64, 3-stage ----------------
// MODE 1: bf16 out. MODE 2: fp32 + softplus cols<16.
#define ABYTES 18432            // 128 rows * 144B

template<int NT>
__device__ __forceinline__ void gemm_stage64(uint32_t st,
                                             const __nv_bfloat16* __restrict__ A,
                                             const __nv_bfloat16* __restrict__ Bw,
                                             int row0, int col0, int K, int k0, int tid)
{
#pragma unroll
    for (int p = 0; p < 4; p++) {
        int i = tid + p * 256;
        int r = i >> 3, cc = (i & 7) << 4;
        CP_ASYNC16(st + r * 144 + cc, (const char*)(A + (size_t)(row0 + r) * K + k0) + cc);
    }
#pragma unroll
    for (int p = 0; p < NT / 32; p++) {
        int i = tid + p * 256;
        int r = i >> 3, cc = (i & 7) << 4;
        CP_ASYNC16(st + ABYTES + r * 144 + cc, (const char*)(Bw + (size_t)(col0 + r) * K + k0) + cc);
    }
}

template<int NT, int MODE>
__global__ __launch_bounds__(256, 2) void gemm_bf16_kernel(
    const __nv_bfloat16* __restrict__ A, const __nv_bfloat16* __restrict__ Bw,
    const float* __restrict__ bias, void* __restrict__ Cv,
    int N, int K)
{
    constexpr int WNJ    = 4;
    constexpr int WNSPAN = 32;
    constexpr int SSTAGE = (128 + NT) * 144;
    constexpr int WMI_E  = (NT == 32) ? 1 : 4;

    extern __shared__ char smem[];
    uint32_t sb = smem_u32(smem);

    int tid  = threadIdx.x;
    int lane = tid & 31;
    int warp = tid >> 5;
    int wm   = (NT >= 128) ? (warp >> 2) : warp;
    int wn   = (NT >= 128) ? (warp & 3) : 0;
    int row0 = blockIdx.y * 128;
    int col0 = blockIdx.x * NT;
    int grp  = lane >> 2;
    int qid  = lane & 3;

    float acc[WMI_E][WNJ][4];
#pragma unroll
    for (int i = 0; i < WMI_E; i++)
#pragma unroll
        for (int j = 0; j < WNJ; j++)
#pragma unroll
            for (int r = 0; r < 4; r++) acc[i][j][r] = 0.f;

    int NC = K / 64;
    gemm_stage64<NT>(sb, A, Bw, row0, col0, K, 0, tid);            CP_COMMIT();
    gemm_stage64<NT>(sb + SSTAGE, A, Bw, row0, col0, K, 64, tid);  CP_COMMIT();

    int a_row  = wm * (WMI_E * 16) + (lane & 15);
    int a_koff = (lane >> 4) << 4;
    int b_row0 = wn * WNSPAN + ((lane >> 4) << 3) + (lane & 7);
    int b_koff = ((lane >> 3) & 1) << 4;

    for (int c = 0; c < NC; c++) {
        CP_WAIT1();
        __syncthreads();
        if (c + 2 < NC)
            gemm_stage64<NT>(sb + ((c + 2) % 3) * SSTAGE, A, Bw, row0, col0, K, (c + 2) * 64, tid);
        CP_COMMIT();
        uint32_t stA = sb + (c % 3) * SSTAGE;
        uint32_t stB = stA + ABYTES;
#pragma unroll
        for (int ks = 0; ks < 4; ks++) {
            uint32_t af[WMI_E][4];
#pragma unroll
            for (int i = 0; i < WMI_E; i++) {
                uint32_t addr = stA + (a_row + i * 16) * 144 + ks * 32 + a_koff;
                asm volatile("ldmatrix.sync.aligned.m8n8.x4.shared.b16 {%0,%1,%2,%3}, [%4];"
                             : "=r"(af[i][0]), "=r"(af[i][1]), "=r"(af[i][2]), "=r"(af[i][3])
                             : "r"(addr));
            }
            uint32_t bf_[2][4];
#pragma unroll
            for (int jj = 0; jj < 2; jj++) {
                uint32_t addr = stB + (b_row0 + jj * 16) * 144 + ks * 32 + b_koff;
                asm volatile("ldmatrix.sync.aligned.m8n8.x4.shared.b16 {%0,%1,%2,%3}, [%4];"
                             : "=r"(bf_[jj][0]), "=r"(bf_[jj][1]), "=r"(bf_[jj][2]), "=r"(bf_[jj][3])
                             : "r"(addr));
            }
#pragma unroll
            for (int i = 0; i < WMI_E; i++)
#pragma unroll
                for (int j = 0; j < WNJ; j++) {
                    asm volatile(
                        "mma.sync.aligned.m16n8k16.row.col.f32.bf16.bf16.f32 "
                        "{%0,%1,%2,%3}, {%4,%5,%6,%7}, {%8,%9}, {%0,%1,%2,%3};"
                        : "+f"(acc[i][j][0]), "+f"(acc[i][j][1]),
                          "+f"(acc[i][j][2]), "+f"(acc[i][j][3])
                        : "r"(af[i][0]), "r"(af[i][1]), "r"(af[i][2]), "r"(af[i][3]),
                          "r"(bf_[j >> 1][(j & 1) * 2]), "r"(bf_[j >> 1][(j & 1) * 2 + 1]));
                }
        }
        __syncthreads();
    }

#pragma unroll
    for (int i = 0; i < WMI_E; i++) {
        int rg0 = row0 + wm * (WMI_E * 16) + i * 16 + grp;
#pragma unroll
        for (int j = 0; j < WNJ; j++) {
            int cg = col0 + wn * WNSPAN + j * 8 + qid * 2;
            float b0 = bias[cg], b1 = bias[cg + 1];
            float v00 = acc[i][j][0] + b0, v01 = acc[i][j][1] + b1;
            float v10 = acc[i][j][2] + b0, v11 = acc[i][j][3] + b1;
            if (MODE == 2 && j < 2) {
                v00 = (v00 > 20.f) ? v00 : log1pf(__expf(v00));
                v01 = (v01 > 20.f) ? v01 : log1pf(__expf(v01));
                v10 = (v10 > 20.f) ? v10 : log1pf(__expf(v10));
                v11 = (v11 > 20.f) ? v11 : log1pf(__expf(v11));
            }
            if (MODE == 1) {
                __nv_bfloat16* Cb = (__nv_bfloat16*)Cv;
                *(uint32_t*)&Cb[(size_t)rg0 * N + cg]       = packbf(v00, v01);
                *(uint32_t*)&Cb[(size_t)(rg0 + 8) * N + cg] = packbf(v10, v11);
            } else {
                float* C = (float*)Cv;
                *(float2*)&C[(size_t)rg0 * N + cg]       = make_float2(v00, v01);
                *(float2*)&C[(size_t)(rg0 + 8) * N + cg] = make_float2(v10, v11);
            }
        }
    }
}

// ---------------- out_proj + residual + LayerNorm, M=64 x N=256, 2-stage, occ 2 ----------------
#define OP_ABYTES (64 * 144)                 // 9216
#define OP_SSTAGE ((64 + 256) * 144)         // 46080
#define OP_SMEM   (2 * OP_SSTAGE)            // 92160

__device__ __forceinline__ void outproj_stage(uint32_t st,
                                              const __nv_bfloat16* __restrict__ A,
                                              const __nv_bfloat16* __restrict__ Bw,
                                              int row0, int k0, int tid)
{
#pragma unroll
    for (int p = 0; p < 2; p++) {
        int i = tid + p * 256;
        int r = i >> 3, cc = (i & 7) << 4;
        CP_ASYNC16(st + r * 144 + cc,
                   (const char*)(A + (size_t)(row0 + r) * DINNER + k0) + cc);
    }
#pragma unroll
    for (int p = 0; p < 8; p++) {
        int i = tid + p * 256;
        int r = i >> 3, cc = (i & 7) << 4;
        CP_ASYNC16(st + OP_ABYTES + r * 144 + cc,
                   (const char*)(Bw + (size_t)r * DINNER + k0) + cc);
    }
}

__global__ __launch_bounds__(256, 2) void outproj_ln_kernel(
    const __nv_bfloat16* __restrict__ A, const __nv_bfloat16* __restrict__ Bw,
    const float* __restrict__ bias, float* __restrict__ Xr,
    const float* __restrict__ gam, const float* __restrict__ bet,
    __nv_bfloat16* __restrict__ mirror)
{
    extern __shared__ char smem[];
    uint32_t sb = smem_u32(smem);

    int tid  = threadIdx.x;
    int lane = tid & 31;
    int warp = tid >> 5;
    int wm   = warp >> 2;          // 0..1  (32 rows each)
    int wn   = warp & 3;           // 0..3  (64 cols each)
    int row0 = blockIdx.x * 64;
    int grp  = lane >> 2;
    int qid  = lane & 3;

    float acc[2][8][4];
#pragma unroll
    for (int i = 0; i < 2; i++)
#pragma unroll
        for (int j = 0; j < 8; j++)
#pragma unroll
            for (int r = 0; r < 4; r++) acc[i][j][r] = 0.f;

    const int NC = DINNER / 64;    // 8
    outproj_stage(sb, A, Bw, row0, 0, tid);             CP_COMMIT();
    outproj_stage(sb + OP_SSTAGE, A, Bw, row0, 64, tid); CP_COMMIT();

    int a_row  = wm * 32 + (lane & 15);
    int a_koff = (lane >> 4) << 4;
    int b_row0 = wn * 64 + ((lane >> 4) << 3) + (lane & 7);
    int b_koff = ((lane >> 3) & 1) << 4;

    for (int c = 0; c < NC; c++) {
        CP_WAIT1();
        __syncthreads();
        uint32_t stA = sb + (c & 1) * OP_SSTAGE;
        uint32_t stB = stA + OP_ABYTES;
#pragma unroll
        for (int ks = 0; ks < 4; ks++) {
            uint32_t af[2][4];
#pragma unroll
            for (int i = 0; i < 2; i++) {
                uint32_t addr = stA + (a_row + i * 16) * 144 + ks * 32 + a_koff;
                asm volatile("ldmatrix.sync.aligned.m8n8.x4.shared.b16 {%0,%1,%2,%3}, [%4];"
                             : "=r"(af[i][0]), "=r"(af[i][1]), "=r"(af[i][2]), "=r"(af[i][3])
                             : "r"(addr));
            }
            uint32_t bf_[4][4];
#pragma unroll
            for (int jj = 0; jj < 4; jj++) {
                uint32_t addr = stB + (b_row0 + jj * 16) * 144 + ks * 32 + b_koff;
                asm volatile("ldmatrix.sync.aligned.m8n8.x4.shared.b16 {%0,%1,%2,%3}, [%4];"
                             : "=r"(bf_[jj][0]), "=r"(bf_[jj][1]), "=r"(bf_[jj][2]), "=r"(bf_[jj][3])
                             : "r"(addr));
            }
#pragma unroll
            for (int i = 0; i < 2; i++)
#pragma unroll
                for (int j = 0; j < 8; j++) {
                    asm volatile(
                        "mma.sync.aligned.m16n8k16.row.col.f32.bf16.bf16.f32 "
                        "{%0,%1,%2,%3}, {%4,%5,%6,%7}, {%8,%9}, {%0,%1,%2,%3};"
                        : "+f"(acc[i][j][0]), "+f"(acc[i][j][1]),
                          "+f"(acc[i][j][2]), "+f"(acc[i][j][3])
                        : "r"(af[i][0]), "r"(af[i][1]), "r"(af[i][2]), "r"(af[i][3]),
                          "r"(bf_[j >> 1][(j & 1) * 2]), "r"(bf_[j >> 1][(j & 1) * 2 + 1]));
                }
        }
        __syncthreads();
        if (c + 2 < NC)
            outproj_stage(sb + (c & 1) * OP_SSTAGE, A, Bw, row0, (c + 2) * 64, tid);
        CP_COMMIT();
    }

    // ---- epilogue: bias + residual + LayerNorm ----
#pragma unroll
    for (int i = 0; i < 2; i++) {
        int r0 = row0 + wm * 32 + i * 16 + grp;
#pragma unroll
        for (int j = 0; j < 8; j++) {
            int cg = wn * 64 + j * 8 + qid * 2;
            float b0 = bias[cg], b1 = bias[cg + 1];
            float2 x0 = *(const float2*)&Xr[(size_t)r0 * DMODEL + cg];
            float2 x1 = *(const float2*)&Xr[(size_t)(r0 + 8) * DMODEL + cg];
            acc[i][j][0] += b0 + x0.x;
            acc[i][j][1] += b1 + x0.y;
            acc[i][j][2] += b0 + x1.x;
            acc[i][j][3] += b1 + x1.y;
        }
    }
    float2* sred = (float2*)smem;   // [64 rows][4 wn]
#pragma unroll
    for (int i = 0; i < 2; i++) {
        float s0 = 0.f, q0 = 0.f, s1 = 0.f, q1 = 0.f;
#pragma unroll
        for (int j = 0; j < 8; j++) {
            s0 += acc[i][j][0] + acc[i][j][1];
            q0 += acc[i][j][0] * acc[i][j][0] + acc[i][j][1] * acc[i][j][1];
            s1 += acc[i][j][2] + acc[i][j][3];
            q1 += acc[i][j][2] * acc[i][j][2] + acc[i][j][3] * acc[i][j][3];
        }
        s0 += __shfl_xor_sync(0xFFFFFFFF, s0, 1); s0 += __shfl_xor_sync(0xFFFFFFFF, s0, 2);
        q0 += __shfl_xor_sync(0xFFFFFFFF, q0, 1); q0 += __shfl_xor_sync(0xFFFFFFFF, q0, 2);
        s1 += __shfl_xor_sync(0xFFFFFFFF, s1, 1); s1 += __shfl_xor_sync(0xFFFFFFFF, s1, 2);
        q1 += __shfl_xor_sync(0xFFFFFFFF, q1, 1); q1 += __shfl_xor_sync(0xFFFFFFFF, q1, 2);
        if (qid == 0) {
            int lr = wm * 32 + i * 16 + grp;
            sred[lr * 4 + wn]       = make_float2(s0, q0);
            sred[(lr + 8) * 4 + wn] = make_float2(s1, q1);
        }
    }
    __syncthreads();
#pragma unroll
    for (int i = 0; i < 2; i++) {
        int lr0 = wm * 32 + i * 16 + grp;
        float mu[2], rs[2];
#pragma unroll
        for (int rr = 0; rr < 2; rr++) {
            int lr = lr0 + rr * 8;
            float2 p0 = sred[lr * 4 + 0], p1 = sred[lr * 4 + 1];
            float2 p2 = sred[lr * 4 + 2], p3 = sred[lr * 4 + 3];
            float S  = p0.x + p1.x + p2.x + p3.x;
            float SS = p0.y + p1.y + p2.y + p3.y;
            float m  = S * (1.f / DMODEL);
            float v  = SS * (1.f / DMODEL) - m * m;
            mu[rr] = m;
            rs[rr] = rsqrtf(v + LN_EPS);
        }
        int r0 = row0 + lr0;
#pragma unroll
        for (int j = 0; j < 8; j++) {
            int cg = wn * 64 + j * 8 + qid * 2;
            float g0 = gam[cg], g1 = gam[cg + 1];
            float t0 = bet[cg], t1 = bet[cg + 1];
            float o00 = (acc[i][j][0] - mu[0]) * rs[0] * g0 + t0;
            float o01 = (acc[i][j][1] - mu[0]) * rs[0] * g1 + t1;
            float o10 = (acc[i][j][2] - mu[1]) * rs[1] * g0 + t0;
            float o11 = (acc[i][j][3] - mu[1]) * rs[1] * g1 + t1;
            *(float2*)&Xr[(size_t)r0 * DMODEL + cg]       = make_float2(o00, o01);
            *(float2*)&Xr[(size_t)(r0 + 8) * DMODEL + cg] = make_float2(o10, o11);
            *(uint32_t*)&mirror[(size_t)r0 * DMODEL + cg]       = packbf(o00, o01);
            *(uint32_t*)&mirror[(size_t)(r0 + 8) * DMODEL + cg] = packbf(o10, o11);
        }
    }
}

// ---------------- depthwise causal conv(4) + silu ----------------
__global__ void conv_silu_kernel(const float* __restrict__ cw,
                                 const float* __restrict__ cb, int l)
{
    int idx = blockIdx.x * blockDim.x + threadIdx.x;
    if (idx >= (TOKENS / 4) * 128) return;
    int g128 = idx & 127;
    int q    = idx >> 7;
    int t0   = q * 4;
    int b    = t0 / SEQ;
    int s0   = t0 % SEQ;
    int c    = g128 * 4;

    float4 w0 = *(const float4*)&cw[(l * DINNER + c + 0) * DCONV];
    float4 w1 = *(const float4*)&cw[(l * DINNER + c + 1) * DCONV];
    float4 w2 = *(const float4*)&cw[(l * DINNER + c + 2) * DCONV];
    float4 w3 = *(const float4*)&cw[(l * DINNER + c + 3) * DCONV];
    float wa[4][4] = {{w0.x,w0.y,w0.z,w0.w},{w1.x,w1.y,w1.z,w1.w},
                      {w2.x,w2.y,w2.z,w2.w},{w3.x,w3.y,w3.z,w3.w}};
    float bs0 = cb[l * DINNER + c + 0];
    float bs1 = cb[l * DINNER + c + 1];
    float bs2 = cb[l * DINNER + c + 2];
    float bs3 = cb[l * DINNER + c + 3];

    float rowv[7][4];
#pragma unroll
    for (int k = 0; k < 7; k++) {
        int s = s0 - 3 + k;
        if (s >= 0) {
            uint2 v = *(const uint2*)&g_xz[(size_t)(b * SEQ + s) * 2 * DINNER + c];
            float2 p0 = __bfloat1622float2(*(__nv_bfloat162*)&v.x);
            float2 p1 = __bfloat1622float2(*(__nv_bfloat162*)&v.y);
            rowv[k][0] = p0.x; rowv[k][1] = p0.y; rowv[k][2] = p1.x; rowv[k][3] = p1.y;
        } else {
            rowv[k][0] = rowv[k][1] = rowv[k][2] = rowv[k][3] = 0.f;
        }
    }
#pragma unroll
    for (int t = 0; t < 4; t++) {
        float o0 = bs0, o1 = bs1, o2 = bs2, o3 = bs3;
#pragma unroll
        for (int k = 0; k < DCONV; k++) {
            o0 += rowv[t + k][0] * wa[0][k];
            o1 += rowv[t + k][1] * wa[1][k];
            o2 += rowv[t + k][2] * wa[2][k];
            o3 += rowv[t + k][3] * wa[3][k];
        }
        o0 = o0 * (1.f / (1.f + __expf(-o0)));
        o1 = o1 * (1.f / (1.f + __expf(-o1)));
        o2 = o2 * (1.f / (1.f + __expf(-o2)));
        o3 = o3 * (1.f / (1.f + __expf(-o3)));
        *(uint2*)&g_xs[(size_t)(b * SEQ + s0 + t) * DINNER + c] =
            make_uint2(packbf(o0, o1), packbf(o2, o3));
    }
}

// ---------------- selective scan: cp.async chunked SMEM pipeline ----------------
#define SCH 18
#define SST 11520

__device__ __forceinline__ void scan_stage(uint32_t dst, int b, int d0, int t0, int tid)
{
    const char* ssrc = (const char*)(g_ssm + (size_t)(b * SEQ + t0) * 32);
#pragma unroll 2
    for (int i = tid; i < 144; i += 128)
        CP_ASYNC16(dst + i * 16, ssrc + i * 16);
#pragma unroll 3
    for (int i = tid; i < 288; i += 128) {
        int r = i >> 4, o = (i & 15) << 4;
        CP_ASYNC16(dst + 2304 + r * 256 + o,
                   (const char*)(g_xs + (size_t)(b * SEQ + t0 + r) * DINNER + d0) + o);
    }
#pragma unroll 3
    for (int i = tid; i < 288; i += 128) {
        int r = i >> 4, o = (i & 15) << 4;
        CP_ASYNC16(dst + 6912 + r * 256 + o,
                   (const char*)(g_xz + (size_t)(b * SEQ + t0 + r) * 2 * DINNER + DINNER + d0) + o);
    }
}

__global__ __launch_bounds__(128) void scan_kernel(const float* __restrict__ A_log,
                                                   const float* __restrict__ Dp, int l)
{
    extern __shared__ char ssm_smem[];
    uint32_t sb = smem_u32(ssm_smem);
    int tid = threadIdx.x;
    int b   = blockIdx.x;
    int d0  = blockIdx.y * 128;
    int d   = d0 + tid;

    const float* Al = A_log + (size_t)(l * DINNER + d) * DSTATE;
    float a2[DSTATE];
#pragma unroll
    for (int n = 0; n < DSTATE; n++) a2[n] = -__expf(Al[n]) * LOG2E;
    float Dv = Dp[l * DINNER + d];
    float h[DSTATE];
#pragma unroll
    for (int n = 0; n < DSTATE; n++) h[n] = 0.f;

    scan_stage(sb, b, d0, 0, tid);           CP_COMMIT();
    scan_stage(sb + SST, b, d0, SCH, tid);   CP_COMMIT();

    int tok0 = b * SEQ;
    for (int c = 0; c < 50; c++) {
        CP_WAIT1();
        __syncthreads();
        int st = (c & 1);
        const float* ssp = (const float*)(ssm_smem + st * SST);
        const __nv_bfloat16* xsp = (const __nv_bfloat16*)(ssm_smem + st * SST + 2304);
        const __nv_bfloat16* rsp = (const __nv_bfloat16*)(ssm_smem + st * SST + 6912);
        __nv_bfloat16* yp = g_yb + (size_t)(tok0 + c * SCH) * DINNER + d;

#pragma unroll 2
        for (int t = 0; t < SCH; t++) {
            const float4* sp = (const float4*)(ssp + t * 32);
            float4 d0v = sp[0], d1v = sp[1], d2v = sp[2], d3v = sp[3];
            float4 b0v = sp[4], b1v = sp[5], b2v = sp[6], b3v = sp[7];
            float dl[DSTATE] = {d0v.x,d0v.y,d0v.z,d0v.w, d1v.x,d1v.y,d1v.z,d1v.w,
                                d2v.x,d2v.y,d2v.z,d2v.w, d3v.x,d3v.y,d3v.z,d3v.w};
            float bm[DSTATE] = {b0v.x,b0v.y,b0v.z,b0v.w, b1v.x,b1v.y,b1v.z,b1v.w,
                                b2v.x,b2v.y,b2v.z,b2v.w, b3v.x,b3v.y,b3v.z,b3v.w};
            float xv = __bfloat162float(xsp[t * 128 + tid]);
            float rv = __bfloat162float(rsp[t * 128 + tid]);
            float accv = 0.f;
#pragma unroll
            for (int n = 0; n < DSTATE; n++) {
                float e = exp2f(a2[n] * dl[n]);
                h[n] = h[n] * e + xv * bm[n];
                accv += h[n] * bm[n];
            }
            float sl = rv * (1.f / (1.f + __expf(-rv)));
            yp[(size_t)t * DINNER] = __float2bfloat16((accv + Dv * xv) * sl);
        }
        __syncthreads();
        if (c + 2 < 50)
            scan_stage(sb + st * SST, b, d0, (c + 2) * SCH, tid);
        CP_COMMIT();
    }
}

// ---------------- heads ----------------
__global__ void heads_kernel(const float* __restrict__ c1w, const float* __restrict__ c1b,
                             const float* __restrict__ c2w, const float* __restrict__ c2b,
                             const float* __restrict__ q1w, const float* __restrict__ q1b,
                             const float* __restrict__ q2w, const float* __restrict__ q2b,
                             float* __restrict__ out)
{
    __shared__ float fin[DMODEL];
    __shared__ float hc[128], hq[128];
    int b = blockIdx.x, t = threadIdx.x;
    const float* f = g_x + (size_t)(b * SEQ + SEQ - 1) * DMODEL;
    fin[t] = f[t];
    fin[t + 128] = f[t + 128];
    __syncthreads();
    float a1 = c1b[t], a2 = q1b[t];
#pragma unroll 4
    for (int k = 0; k < DMODEL; k++) {
        float fv = fin[k];
        a1 += fv * c1w[k * 128 + t];
        a2 += fv * q1w[k * 128 + t];
    }
    hc[t] = fmaxf(a1, 0.f);
    hq[t] = fmaxf(a2, 0.f);
    __syncthreads();
    if (t == 0) {
        float s = c2b[0];
        for (int k = 0; k < 128; k++) s += hc[k] * c2w[k];
        out[b] = fmaxf(s, 0.f);
    }
    if (t < 10) {
        float s = q2b[t];
        for (int k = 0; k < 128; k++) s += hq[k] * q2w[k * 10 + t];
        out[BATCH + b * 10 + t] = fmaxf(s, 0.f);
    }
}

// ---------------- launch ----------------
extern "C" void kernel_launch(void* const* d_in, const int* in_sizes, int n_in,
                              void* d_out, int out_size)
{
    const int*   grid   = (const int*)  d_in[0];
    const float* ce     = (const float*)d_in[1];
    const float* pe     = (const float*)d_in[2];
    const float* in_w   = (const float*)d_in[3];
    const float* in_b   = (const float*)d_in[4];
    const float* conv_w = (const float*)d_in[5];
    const float* conv_b = (const float*)d_in[6];
    const float* xp_w   = (const float*)d_in[7];
    const float* xp_b   = (const float*)d_in[8];
    const float* A_log  = (const float*)d_in[9];
    const float* Dp     = (const float*)d_in[10];
    const float* out_w  = (const float*)d_in[11];
    const float* out_b  = (const float*)d_in[12];
    const float* ln_g   = (const float*)d_in[13];
    const float* ln_b   = (const float*)d_in[14];
    const float* c1w    = (const float*)d_in[15];
    const float* c1b    = (const float*)d_in[16];
    const float* c2w    = (const float*)d_in[17];
    const float* c2b    = (const float*)d_in[18];
    const float* q1w    = (const float*)d_in[19];
    const float* q1b    = (const float*)d_in[20];
    const float* q2w    = (const float*)d_in[21];
    const float* q2b    = (const float*)d_in[22];
    float* out = (float*)d_out;

    __nv_bfloat16 *pxb, *pyb, *pxz, *pxs;
    uint32_t *pwbi, *pwbo, *pwbx;
    float *px, *pssm;
    cudaGetSymbolAddress((void**)&px,   g_x);
    cudaGetSymbolAddress((void**)&pxb,  g_xb);
    cudaGetSymbolAddress((void**)&pyb,  g_yb);
    cudaGetSymbolAddress((void**)&pxz,  g_xz);
    cudaGetSymbolAddress((void**)&pxs,  g_xs);
    cudaGetSymbolAddress((void**)&pssm, g_ssm);
    cudaGetSymbolAddress((void**)&pwbi, g_wbi);
    cudaGetSymbolAddress((void**)&pwbo, g_wbo);
    cudaGetSymbolAddress((void**)&pwbx, g_wbx);

    const int SM128 = 3 * (128 + 128) * 144;   // 110592
    const int SM32  = 3 * (128 + 32) * 144;    // 69120
    cudaFuncSetAttribute(gemm_bf16_kernel<128, 1>, cudaFuncAttributeMaxDynamicSharedMemorySize, SM128);
    cudaFuncSetAttribute(gemm_bf16_kernel<32, 2>,  cudaFuncAttributeMaxDynamicSharedMemorySize, SM32);
    cudaFuncSetAttribute(outproj_ln_kernel,        cudaFuncAttributeMaxDynamicSharedMemorySize, OP_SMEM);

    // converts (2) + embed (1) -> launch #4 = in_proj (ncu capture target)
    {
        int nA = NLAYERS * 2 * DINNER * (DMODEL / 2);
        convert_in_w_kernel<<<(nA + 255) / 256, 256>>>(in_w, pwbi);
        int nOX = NLAYERS * (DMODEL * (DINNER / 2) + 32 * (DINNER / 2));
        convert_oxw_kernel<<<(nOX + 255) / 256, 256>>>(out_w, pwbo, xp_w, pwbx);
        int n = TOKENS * (DMODEL / 4);
        embed_kernel<<<(n + 255) / 256, 256>>>(grid, ce, pe);
    }

    for (int l = 0; l < NLAYERS; l++) {
        // in_proj: (T x 256) -> 1024, bf16 out
        gemm_bf16_kernel<128, 1><<<dim3(8, TOKENS / 128), 256, SM128>>>(
            pxb, (const __nv_bfloat16*)(pwbi + (size_t)l * 2 * DINNER * (DMODEL / 2)),
            in_b + l * 2 * DINNER, pxz, 2 * DINNER, DMODEL);

        {
            int n = (TOKENS / 4) * 128;
            conv_silu_kernel<<<(n + 255) / 256, 256>>>(conv_w, conv_b, l);
        }

        // xproj: (T x 512) -> 32, softplus fused
        gemm_bf16_kernel<32, 2><<<dim3(1, TOKENS / 128), 256, SM32>>>(
            pxs, (const __nv_bfloat16*)(pwbx + (size_t)l * 32 * (DINNER / 2)),
            xp_b + l * 32, pssm, 32, DINNER);

        scan_kernel<<<dim3(BATCH, DINNER / 128), 128, 2 * SST>>>(A_log, Dp, l);

        // out_proj fused: M=64 tiles, occ 2, bias + residual + LN
        outproj_ln_kernel<<<TOKENS / 64, 256, OP_SMEM>>>(
            pyb, (const __nv_bfloat16*)(pwbo + (size_t)l * DMODEL * (DINNER / 2)),
            out_b + l * DMODEL, px, ln_g, ln_b, pxb);
    }

    heads_kernel<<<BATCH, 128>>>(c1w, c1b, c2w, c2b, q1w, q1b, q2w, q2b, out);
}